// round 1
// baseline (speedup 1.0000x reference)
#include <cuda_runtime.h>

// RFFT2d: x (32,1,1024,1024) fp32 -> out (32, 16384, 8, 5, 2) fp32
// 8-point real FFT along each row-of-8 inside non-overlapping 8x8 blocks,
// scaled by 1/64. One thread per (n, block, row): reads 8 floats (2x float4),
// writes 10 floats (5x float2, contiguous in output order -> coalesced).

#define N_TOTAL (32u * 16384u * 8u)   // 4,194,304 rows

__global__ __launch_bounds__(256) void rfft8_kernel(
    const float* __restrict__ x, float* __restrict__ out)
{
    unsigned t = blockIdx.x * blockDim.x + threadIdx.x;
    if (t >= N_TOTAL) return;

    unsigned r  = t & 7u;           // row within block (0..7)
    unsigned k  = (t >> 3) & 16383u; // block index within image (0..16383)
    unsigned n  = t >> 17;          // batch (0..31)
    unsigned bh = k >> 7;           // block row (0..127)
    unsigned bw = k & 127u;         // block col (0..127)

    // input offset: n*1024*1024 + (bh*8+r)*1024 + bw*8
    size_t in_off = ((size_t)n << 20) + (((size_t)(bh * 8u + r)) << 10) + ((size_t)bw << 3);
    const float4* p = reinterpret_cast<const float4*>(x + in_off);
    float4 a = p[0];
    float4 b = p[1];

    float x0 = a.x, x1 = a.y, x2 = a.z, x3 = a.w;
    float x4 = b.x, x5 = b.y, x6 = b.z, x7 = b.w;

    // radix-2 split
    float e0 = x0 + x4, o0 = x0 - x4;
    float e1 = x1 + x5, o1 = x1 - x5;
    float e2 = x2 + x6, o2 = x2 - x6;
    float e3 = x3 + x7, o3 = x3 - x7;

    const float c = 0.70710678118654752440f; // sqrt(2)/2
    const float s = 1.0f / 64.0f;

    float F0  = (e0 + e2) + (e1 + e3);
    float F4  = (e0 + e2) - (e1 + e3);
    float F2r = e0 - e2;
    float F2i = e3 - e1;

    float d13  = o1 - o3;   //  x1 - x5 - x3 + x7
    float m13  = o1 + o3;   //  x1 - x5 + x3 - x7
    float F1r = o0 + c * d13;
    float F3r = o0 - c * d13;
    float F1i = -o2 - c * m13;
    float F3i =  o2 - c * m13;

    float2* o = reinterpret_cast<float2*>(out + (size_t)t * 10u);
    o[0] = make_float2(F0  * s, 0.0f);
    o[1] = make_float2(F1r * s, F1i * s);
    o[2] = make_float2(F2r * s, F2i * s);
    o[3] = make_float2(F3r * s, F3i * s);
    o[4] = make_float2(F4  * s, 0.0f);
}

extern "C" void kernel_launch(void* const* d_in, const int* in_sizes, int n_in,
                              void* d_out, int out_size)
{
    const float* x = (const float*)d_in[0];
    float* out = (float*)d_out;
    (void)in_sizes; (void)n_in; (void)out_size;

    dim3 block(256);
    dim3 grid(N_TOTAL / 256);
    rfft8_kernel<<<grid, block>>>(x, out);
}

// round 3
// speedup vs baseline: 1.6645x; 1.6645x over previous
#include <cuda_runtime.h>

// RFFT2d: x (32,1,1024,1024) fp32 -> out (32, 16384, 8, 5, 2) fp32
// 8-point real FFT along rows-of-8 inside non-overlapping 8x8 blocks, /64.
//
// Block = 256 threads handles 256 consecutive output rows (one tile:
// 32 blocks x 8 rows, fixed n/bh). All global traffic is coalesced float4;
// redistribution happens in shared memory with an XOR swizzle on the input
// side (conflict-free LDS.128) and a naturally conflict-free 40B-stride
// STS.64 on the output side.

#define N_TOTAL (32u * 16384u * 8u)   // 4,194,304 rows-of-8

__global__ __launch_bounds__(256) void rfft8_kernel(
    const float* __restrict__ x, float* __restrict__ out)
{
    __shared__ float4 s_in[512];     // 8 KB  (swizzled)
    __shared__ float  s_out[2560];   // 10 KB

    unsigned tid = threadIdx.x;
    unsigned t0  = blockIdx.x * 256u;          // first output row of tile
    unsigned n   = t0 >> 17;                   // batch
    unsigned k0  = (t0 >> 3) & 16383u;         // first block index
    unsigned bh  = k0 >> 7;                    // block row (0..127)
    unsigned bw0 = k0 & 127u;                  // first block col (mult of 32)

    // ---- Phase 1: coalesced global load -> swizzled smem ----
    // 8 row segments, each 256 contiguous floats (64 float4).
    const float4* gin = reinterpret_cast<const float4*>(x);
    // float4 index of segment r: n*2^18 + (bh*8+r)*256 + bw0*2
    unsigned gbase4 = (n << 18) + ((bh << 3) << 8) + (bw0 << 1);

    #pragma unroll
    for (int i = 0; i < 2; i++) {
        unsigned q  = tid + (unsigned)i * 256u;   // 0..511
        unsigned r  = q >> 6;                     // segment (row in 8x8 block)
        unsigned c4 = q & 63u;                    // float4 within segment
        float4 v = gin[gbase4 + (r << 8) + c4];
        s_in[q ^ r] = v;                          // swizzle pos = q ^ (q>>6)
    }
    __syncthreads();

    // ---- Phase 2: per-thread 8-point rFFT ----
    // Thread handles local row lr = tid: block jb = tid>>3, row r = tid&7.
    {
        unsigned jb = tid >> 3;
        unsigned r  = tid & 7u;
        unsigned q0 = (r << 6) + (jb << 1);       // float4 index (linear)
        float4 a = s_in[q0 ^ r];
        float4 b = s_in[(q0 + 1u) ^ r];

        float x0 = a.x, x1 = a.y, x2 = a.z, x3 = a.w;
        float x4 = b.x, x5 = b.y, x6 = b.z, x7 = b.w;

        float e0 = x0 + x4, o0 = x0 - x4;
        float e1 = x1 + x5, o1 = x1 - x5;
        float e2 = x2 + x6, o2 = x2 - x6;
        float e3 = x3 + x7, o3 = x3 - x7;

        const float c = 0.70710678118654752440f; // sqrt(2)/2
        const float s = 1.0f / 64.0f;

        float F0  = (e0 + e2) + (e1 + e3);
        float F4  = (e0 + e2) - (e1 + e3);
        float F2r = e0 - e2;
        float F2i = e3 - e1;

        float d13 = o1 - o3;
        float m13 = o1 + o3;
        float F1r = o0 + c * d13;
        float F3r = o0 - c * d13;
        float F1i = -o2 - c * m13;
        float F3i =  o2 - c * m13;

        // stage 10 floats at float offset tid*10 (8B aligned)
        float2* so = reinterpret_cast<float2*>(&s_out[tid * 10u]);
        so[0] = make_float2(F0  * s, 0.0f);
        so[1] = make_float2(F1r * s, F1i * s);
        so[2] = make_float2(F2r * s, F2i * s);
        so[3] = make_float2(F3r * s, F3i * s);
        so[4] = make_float2(F4  * s, 0.0f);
    }
    __syncthreads();

    // ---- Phase 3: coalesced global store ----
    // Tile output = 2560 floats = 640 float4, base float = t0*10 (16B aligned).
    float4* gout = reinterpret_cast<float4*>(out + (size_t)t0 * 10u);
    const float4* so4 = reinterpret_cast<const float4*>(s_out);
    gout[tid]        = so4[tid];
    gout[tid + 256]  = so4[tid + 256];
    if (tid < 128u)
        gout[tid + 512] = so4[tid + 512];
}

extern "C" void kernel_launch(void* const* d_in, const int* in_sizes, int n_in,
                              void* d_out, int out_size)
{
    const float* x = (const float*)d_in[0];
    float* out = (float*)d_out;
    (void)in_sizes; (void)n_in; (void)out_size;

    rfft8_kernel<<<N_TOTAL / 256u, 256>>>(x, out);
}